// round 2
// baseline (speedup 1.0000x reference)
#include <cuda_runtime.h>
#include <cuda_bf16.h>
#include <cstdint>

#define BINS 20
#define NODES 21
#define NWARPS 8
#define THREADS 256
#define MAXBLOCKS 592
#define SLOTS (2 * BINS)
#define FRAC_SCALE 2097152.0f   /* 2^21 */
#define INV_FRAC_SCALE (1.0f/2097152.0f)
#define COUNT_SHIFT 44

// Per-block partial histograms (overwritten every launch; no zeroing needed).
__device__ unsigned long long g_part[MAXBLOCKS][SLOTS];
// Completion counter. Zero-initialized at module load; the last block resets
// it to 0 every launch, so replays are deterministic.
__device__ unsigned int g_done;

__device__ __forceinline__ void hx_accum(unsigned long long* my, float x, int g) {
    float t = x * (float)BINS;
    int k = (int)t;
    if (k > BINS - 1) k = BINS - 1;
    if (k < 0) k = 0;
    float frac = t - (float)k;
    frac = fminf(fmaxf(frac, 0.0f), 1.0f);
    unsigned long long pk = (1ULL << COUNT_SHIFT)
        | (unsigned long long)(frac * FRAC_SCALE + 0.5f);
    atomicAdd(&my[(g & 1) * BINS + k], pk);
}

__global__ __launch_bounds__(THREADS)
void hx_fused(const float* __restrict__ yp, const int* __restrict__ s, int n,
              const float* __restrict__ p_a, const float* __restrict__ p_b,
              float* __restrict__ out) {
    __shared__ unsigned long long sh[NWARPS][SLOTS];
    __shared__ bool s_last;
    const int tid = threadIdx.x;
    const int warp = tid >> 5;

    for (int i = tid; i < NWARPS * SLOTS; i += THREADS)
        (&sh[0][0])[i] = 0ULL;
    __syncthreads();

    unsigned long long* my = sh[warp];

    const int nvec = n >> 2;
    const float4* __restrict__ yp4 = (const float4*)yp;
    const int4*   __restrict__ s4p = (const int4*)s;
    const int stride = gridDim.x * THREADS;

    for (int i = blockIdx.x * THREADS + tid; i < nvec; i += stride) {
        float4 x4 = yp4[i];
        int4   g4 = s4p[i];
        hx_accum(my, x4.x, g4.x);
        hx_accum(my, x4.y, g4.y);
        hx_accum(my, x4.z, g4.z);
        hx_accum(my, x4.w, g4.w);
    }

    // tail (n not divisible by 4)
    {
        int rem_base = nvec << 2;
        int gtid = blockIdx.x * THREADS + tid;
        if (gtid < n - rem_base) {
            int idx = rem_base + gtid;
            hx_accum(my, yp[idx], s[idx]);
        }
    }

    __syncthreads();
    // Block partial: reduce warp copies, store to this block's global slot.
    for (int i = tid; i < SLOTS; i += THREADS) {
        unsigned long long acc = 0ULL;
        #pragma unroll
        for (int w = 0; w < NWARPS; w++) acc += sh[w][i];
        g_part[blockIdx.x][i] = acc;
    }

    // Elect last block.
    __threadfence();
    if (tid == 0) {
        unsigned int prev = atomicAdd(&g_done, 1u);
        s_last = (prev == gridDim.x - 1);
    }
    __syncthreads();
    if (!s_last) return;

    // ---- Last block: reduce all partials, then compute loss ----
    __shared__ unsigned long long s_tot[SLOTS];
    const int nb = gridDim.x;
    if (tid < SLOTS) {
        unsigned long long acc = 0ULL;
        for (int b = 0; b < nb; b++) acc += g_part[b][tid];
        s_tot[tid] = acc;
    }
    __syncthreads();

    if (tid == 0) {
        float cnt[2][BINS], fr[2][BINS];
        for (int g = 0; g < 2; g++) {
            for (int b = 0; b < BINS; b++) {
                unsigned long long h = s_tot[g * BINS + b];
                cnt[g][b] = (float)(h >> COUNT_SHIFT);
                fr[g][b]  = (float)(h & ((1ULL << COUNT_SHIFT) - 1ULL)) * INV_FRAC_SCALE;
            }
        }

        float W[2][NODES];
        for (int g = 0; g < 2; g++) {
            for (int k = 0; k < NODES; k++) {
                float w = 0.0f;
                if (k < BINS) w += cnt[g][k] - fr[g][k];
                if (k > 0)    w += fr[g][k - 1];
                W[g][k] = w;
            }
        }

        float S0 = 0.0f, S1 = 0.0f;
        for (int k = 0; k < NODES; k++) { S0 += W[0][k]; S1 += W[1][k]; }
        float inv0 = (S0 > 0.0f) ? 1.0f / S0 : 0.0f;
        float inv1 = (S1 > 0.0f) ? 1.0f / S1 : 0.0f;

        // Python computes int(20*pct) in double; f32 0.7f*20 = 13.99999976
        // would floor to 13, so snap up with an epsilon before truncation.
        int a_bin = (int)floorf((float)BINS * p_a[0] + 1e-4f);
        int b_bin = (int)floorf((float)BINS * p_b[0] + 1e-4f);

        float loss = 0.0f;
        for (int k = 0; k < NODES; k++) {
            if (k >= a_bin && k < b_bin)
                loss += fabsf(W[0][k] * inv0 - W[1][k] * inv1);
        }
        out[0] = loss;

        // Reset for the next graph replay.
        g_done = 0u;
    }
}

extern "C" void kernel_launch(void* const* d_in, const int* in_sizes, int n_in,
                              void* d_out, int out_size) {
    const float* y_pred = (const float*)d_in[0];
    const int*   s      = (const int*)d_in[1];
    // d_in[2] = y_gt (unused)
    const float* pct_a  = (const float*)d_in[3];
    const float* pct_b  = (const float*)d_in[4];
    float* out = (float*)d_out;
    int n = in_sizes[0];

    int nvec = n >> 2;
    int blocks = (nvec + THREADS - 1) / THREADS;
    if (blocks > 296) blocks = 296;   // one wave: 2 CTAs/SM x 148 SMs
    if (blocks < 1) blocks = 1;

    hx_fused<<<blocks, THREADS>>>(y_pred, s, n, pct_a, pct_b, out);
}

// round 4
// speedup vs baseline: 2.0846x; 2.0846x over previous
#include <cuda_runtime.h>
#include <cuda_bf16.h>
#include <cstdint>

#define BINS 20
#define NODES 21
#define NWARPS 8
#define THREADS 256
#define MAXBLOCKS 592
#define SLOTS (2 * BINS)
#define FRAC_BITS 13
#define FRAC_SCALE 8192.0f          /* 2^13 */
#define INV_FRAC_SCALE (1.0f/8192.0f)
#define CNT_SHIFT 20                /* u32 pack: cnt<<20 | frac13 */

// Per-block partial histograms: (cnt << 32) | frac_sum. Overwritten each launch.
__device__ unsigned long long g_part[MAXBLOCKS][SLOTS];
__device__ unsigned int g_done;   // reset to 0 by last block each launch

__device__ __forceinline__ void hx_accum(unsigned int* my, float x, int g) {
    float t = x * (float)BINS;
    int k = (int)t;
    if (k > BINS - 1) k = BINS - 1;
    if (k < 0) k = 0;
    float frac = t - (float)k;
    frac = fminf(fmaxf(frac, 0.0f), 1.0f);
    unsigned int pk = (1u << CNT_SHIFT) | (unsigned int)(frac * FRAC_SCALE + 0.5f);
    atomicAdd(&my[(g & 1) * BINS + k], pk);
}

__global__ __launch_bounds__(THREADS, 4)
void hx_fused(const float* __restrict__ yp, const int* __restrict__ s, int n,
              const float* __restrict__ p_a, const float* __restrict__ p_b,
              float* __restrict__ out) {
    __shared__ unsigned int sh[NWARPS][SLOTS];
    __shared__ bool s_last;
    const int tid = threadIdx.x;
    const int warp = tid >> 5;

    for (int i = tid; i < NWARPS * SLOTS; i += THREADS)
        (&sh[0][0])[i] = 0u;
    __syncthreads();

    unsigned int* my = sh[warp];

    const int nvec = n >> 2;
    const float4* __restrict__ yp4 = (const float4*)yp;
    const int4*   __restrict__ s4p = (const int4*)s;
    const int stride = gridDim.x * THREADS;

    #pragma unroll 4
    for (int i = blockIdx.x * THREADS + tid; i < nvec; i += stride) {
        float4 x4 = yp4[i];
        int4   g4 = s4p[i];
        hx_accum(my, x4.x, g4.x);
        hx_accum(my, x4.y, g4.y);
        hx_accum(my, x4.z, g4.z);
        hx_accum(my, x4.w, g4.w);
    }

    // tail (n not divisible by 4)
    {
        int rem_base = nvec << 2;
        int gtid = blockIdx.x * THREADS + tid;
        if (gtid < n - rem_base) {
            int idx = rem_base + gtid;
            hx_accum(my, yp[idx], s[idx]);
        }
    }

    __syncthreads();
    // Block partial: unpack+widen warp copies, one u64 store per slot.
    for (int i = tid; i < SLOTS; i += THREADS) {
        unsigned int cnt = 0, fr = 0;
        #pragma unroll
        for (int w = 0; w < NWARPS; w++) {
            unsigned int v = sh[w][i];
            cnt += v >> CNT_SHIFT;
            fr  += v & ((1u << CNT_SHIFT) - 1u);
        }
        g_part[blockIdx.x][i] = ((unsigned long long)cnt << 32) | fr;
    }

    __threadfence();
    if (tid == 0) {
        unsigned int prev = atomicAdd(&g_done, 1u);
        s_last = (prev == gridDim.x - 1);
    }
    __syncthreads();
    if (!s_last) return;
    __threadfence();

    // ---- Last block: parallel reduce of all per-block partials ----
    __shared__ unsigned long long s_cnt[SLOTS], s_fr[SLOTS];
    if (tid < SLOTS) { s_cnt[tid] = 0ULL; s_fr[tid] = 0ULL; }
    __syncthreads();

    const int nb = gridDim.x;
    const int lanes_per_slot = THREADS / SLOTS;            // 6
    if (tid < SLOTS * lanes_per_slot) {
        int slot = tid % SLOTS;
        unsigned long long cnt = 0, fr = 0;
        for (int b = tid / SLOTS; b < nb; b += lanes_per_slot) {
            unsigned long long v = g_part[b][slot];
            cnt += v >> 32;
            fr  += v & 0xFFFFFFFFULL;
        }
        atomicAdd(&s_cnt[slot], cnt);
        atomicAdd(&s_fr[slot], fr);
    }
    __syncthreads();

    if (tid == 0) {
        float cnt[2][BINS], fr[2][BINS];
        for (int g = 0; g < 2; g++) {
            for (int b = 0; b < BINS; b++) {
                cnt[g][b] = (float)s_cnt[g * BINS + b];
                fr[g][b]  = (float)s_fr[g * BINS + b] * INV_FRAC_SCALE;
            }
        }

        float W[2][NODES];
        for (int g = 0; g < 2; g++) {
            for (int k = 0; k < NODES; k++) {
                float w = 0.0f;
                if (k < BINS) w += cnt[g][k] - fr[g][k];
                if (k > 0)    w += fr[g][k - 1];
                W[g][k] = w;
            }
        }

        float S0 = 0.0f, S1 = 0.0f;
        for (int k = 0; k < NODES; k++) { S0 += W[0][k]; S1 += W[1][k]; }
        float inv0 = (S0 > 0.0f) ? 1.0f / S0 : 0.0f;
        float inv1 = (S1 > 0.0f) ? 1.0f / S1 : 0.0f;

        // Python computes int(20*pct) in double; f32 0.7f*20 = 13.99999976
        // would floor to 13, so snap up with an epsilon before truncation.
        int a_bin = (int)floorf((float)BINS * p_a[0] + 1e-4f);
        int b_bin = (int)floorf((float)BINS * p_b[0] + 1e-4f);

        float loss = 0.0f;
        for (int k = 0; k < NODES; k++) {
            if (k >= a_bin && k < b_bin)
                loss += fabsf(W[0][k] * inv0 - W[1][k] * inv1);
        }
        out[0] = loss;

        g_done = 0u;   // deterministic across graph replays
    }
}

extern "C" void kernel_launch(void* const* d_in, const int* in_sizes, int n_in,
                              void* d_out, int out_size) {
    const float* y_pred = (const float*)d_in[0];
    const int*   s      = (const int*)d_in[1];
    // d_in[2] = y_gt (unused)
    const float* pct_a  = (const float*)d_in[3];
    const float* pct_b  = (const float*)d_in[4];
    float* out = (float*)d_out;
    int n = in_sizes[0];

    int nvec = n >> 2;
    int blocks = (nvec + THREADS - 1) / THREADS;
    if (blocks > MAXBLOCKS) blocks = MAXBLOCKS;   // 4 CTAs/SM x 148 SMs
    if (blocks < 1) blocks = 1;

    hx_fused<<<blocks, THREADS>>>(y_pred, s, n, pct_a, pct_b, out);
}